// round 15
// baseline (speedup 1.0000x reference)
#include <cuda_runtime.h>
#include <cuda_bf16.h>
#include <cstdint>

#define BB 8
#define TT 8192
#define DD 512
#define MM 512
#define KIN 544        // DD + 32 fourier dims
#define CH 8           // rows per chunk
#define NC 1024        // TT / CH chunks per batch
#define GRP 8          // chunks per group
#define NG 128         // groups per batch (NC / GRP)
#define D4 128         // DD / 4
#define NROWS (BB*MM)  // 4096 output rows
#define NKS 17         // k32-steps per product (544/32)
#define NIT 51         // 3 products x 17

// combo1 block ranges
#define NB_SUM 512     // sumpre: 2 groups per block
#define NB_WS  1088    // wsplit (KIN*DD/256)
#define NB_F   64      // fourier
#define NB_BND 16      // bounds (4096/256)

// Scratch (allocation-free rule: __device__ globals)
__device__ float g_cpre[BB * NC * DD];        // 16.8 MB within-group exclusive chunk prefix
__device__ float g_gtot[BB * NG * DD];        //  2.1 MB group totals
__device__ float g_gpre[BB * (NG + 1) * DD];  //  2.1 MB exclusive group prefix
__device__ __nv_bfloat16 g_Xhi[NROWS * KIN];  //  4.5 MB X split-high [row][k]
__device__ __nv_bfloat16 g_Xlo[NROWS * KIN];  //  4.5 MB X split-low
__device__ __nv_bfloat16 g_Whi[KIN * DD];     //  0.56 MB W split-high [k][n]
__device__ __nv_bfloat16 g_Wlo[KIN * DD];     //  0.56 MB W split-low
__device__ int2  g_se  [NROWS];               // clamped (s, e) per segment

__device__ __forceinline__ uint32_t smem_u32(const void* p) {
    uint32_t a;
    asm("{ .reg .u64 t; cvta.to.shared.u64 t, %1; cvt.u32.u64 %0, t; }" : "=r"(a) : "l"(p));
    return a;
}

// ---------------------------------------------------------------------------
// K_combo1: ONE launch for all independent front work (block-range dispatch).
// ---------------------------------------------------------------------------
__global__ void __launch_bounds__(256) k_combo1(const float4* __restrict__ fr,
                                                const float* __restrict__ W,
                                                const void* __restrict__ bbv) {
    int bid = blockIdx.x, tid = threadIdx.x;

    if (bid < NB_SUM) {
        int b = bid >> 6;
        int g = (bid & 63) * 2 + (tid >> 7);
        int t = tid & 127;
        const float4* p = fr + (size_t)(b * TT + g * GRP * CH) * D4 + t;
        float4* cp = (float4*)g_cpre + (size_t)(b * NC + g * GRP) * D4 + t;

        float4 run = make_float4(0.f, 0.f, 0.f, 0.f);
#pragma unroll
        for (int c = 0; c < GRP; c++) {
            cp[(size_t)c * D4] = run;
            float4 s = make_float4(0.f, 0.f, 0.f, 0.f);
#pragma unroll
            for (int r = 0; r < CH; r++) {
                float4 v = p[(size_t)(c * CH + r) * D4];
                s.x += v.x; s.y += v.y; s.z += v.z; s.w += v.w;
            }
            run.x += s.x; run.y += s.y; run.z += s.z; run.w += s.w;
        }
        ((float4*)g_gtot)[(size_t)(b * NG + g) * D4 + t] = run;

    } else if (bid < NB_SUM + NB_WS) {
        int i = (bid - NB_SUM) * 256 + tid;
        float v = W[i];
        __nv_bfloat16 h = __float2bfloat16(v);
        g_Whi[i] = h;
        g_Wlo[i] = __float2bfloat16(v - __bfloat162float(h));

    } else if (bid < NB_SUM + NB_WS + NB_F) {
        int m = (bid - NB_SUM - NB_WS) * 8 + (tid >> 5);
        int i = tid & 31;
        const float pos = (float)m * (1.0f / 511.0f);
        const float step = (float)(6.907755278982137 / 15.0);  // log(1000)/15
        int fi = (i < 16) ? i : i - 16;
        float arg = (float)fi * step;
        float freq = (float)exp((double)arg);
        float ang = pos * freq;
        double angd = (double)ang;
        float v = (i < 16) ? (float)sin(angd) : (float)cos(angd);
        __nv_bfloat16 h = __float2bfloat16(v);
        __nv_bfloat16 l = __float2bfloat16(v - __bfloat162float(h));
#pragma unroll
        for (int b = 0; b < BB; b++) {
            size_t idx = (size_t)(b * MM + m) * KIN + DD + i;
            g_Xhi[idx] = h;
            g_Xlo[idx] = l;
        }

    } else {
        __shared__ int s_any;
        if (tid == 0) s_any = 0;
        __syncthreads();
        const unsigned int* bbw = (const unsigned int*)bbv;
        int bad = 0;
        for (int i = 2 * tid + 1; i < BB * MM * 2; i += 2 * 256)
            if (bbw[i] != 0u) bad = 1;
        if (bad) atomicOr(&s_any, 1);
        __syncthreads();
        int is64 = (s_any == 0);

        int bm = (bid - NB_SUM - NB_WS - NB_F) * 256 + tid;
        long long s_raw, e_raw;
        if (is64) {
            const long long* p = (const long long*)bbv;
            s_raw = p[2 * bm]; e_raw = p[2 * bm + 1];
        } else {
            const int* p = (const int*)bbv;
            s_raw = p[2 * bm]; e_raw = p[2 * bm + 1];
        }
        long long sl = s_raw; if (sl < 0) sl = 0; if (sl > TT - 1) sl = TT - 1;
        long long el = e_raw; if (el > TT) el = TT; if (el < sl + 1) el = sl + 1;
        g_se[bm] = make_int2((int)sl, (int)el);
    }
}

// ---------------------------------------------------------------------------
// K2: warp-parallel exclusive prefix over 128 group totals.
// ---------------------------------------------------------------------------
__global__ void __launch_bounds__(256) k_gscan() {
    int wid = threadIdx.x >> 5, l = threadIdx.x & 31;
    int b  = blockIdx.x >> 4;
    int c4 = (blockIdx.x & 15) * 8 + wid;
    const float4* gt = (const float4*)g_gtot + (size_t)b * NG * D4 + c4;
    float4* gp = (float4*)g_gpre + (size_t)b * (NG + 1) * D4 + c4;

    float4 v[4];
    float4 s = make_float4(0.f, 0.f, 0.f, 0.f);
#pragma unroll
    for (int j = 0; j < 4; j++) {
        v[j] = gt[(size_t)(4 * l + j) * D4];
        s.x += v[j].x; s.y += v[j].y; s.z += v[j].z; s.w += v[j].w;
    }
    float4 inc = s;
#pragma unroll
    for (int off = 1; off < 32; off <<= 1) {
        float ux = __shfl_up_sync(0xffffffffu, inc.x, off);
        float uy = __shfl_up_sync(0xffffffffu, inc.y, off);
        float uz = __shfl_up_sync(0xffffffffu, inc.z, off);
        float uw = __shfl_up_sync(0xffffffffu, inc.w, off);
        if (l >= off) { inc.x += ux; inc.y += uy; inc.z += uz; inc.w += uw; }
    }
    float4 run = make_float4(inc.x - s.x, inc.y - s.y, inc.z - s.z, inc.w - s.w);
#pragma unroll
    for (int j = 0; j < 4; j++) {
        gp[(size_t)(4 * l + j) * D4] = run;
        run.x += v[j].x; run.y += v[j].y; run.z += v[j].z; run.w += v[j].w;
    }
    if (l == 31) gp[(size_t)NG * D4] = run;
}

// ---------------------------------------------------------------------------
// K3: per-segment mean -> bf16 hi/lo into g_Xhi/g_Xlo cols 0..511.
// ---------------------------------------------------------------------------
__global__ void __launch_bounds__(128) k_seg(const float4* __restrict__ fr) {
    int bm = blockIdx.x;
    int b = bm >> 9;

    int2 se = g_se[bm];
    int s = se.x, e = se.y;
    int cs = s >> 3, ce = e >> 3;

    int t = threadIdx.x;
    const float4* CP = (const float4*)g_cpre + (size_t)b * NC * D4 + t;
    const float4* GP = (const float4*)g_gpre + (size_t)b * (NG + 1) * D4 + t;

    float4 a = GP[(size_t)(ce >> 3) * D4];
    float4 q = GP[(size_t)(cs >> 3) * D4];
    {
        float4 c1 = CP[(size_t)cs * D4];
        q.x += c1.x; q.y += c1.y; q.z += c1.z; q.w += c1.w;
        if (ce < NC) {
            float4 c2 = CP[(size_t)ce * D4];
            a.x += c2.x; a.y += c2.y; a.z += c2.z; a.w += c2.w;
        }
    }
    a.x -= q.x; a.y -= q.y; a.z -= q.z; a.w -= q.w;

    const float4* fb = fr + (size_t)b * TT * D4 + t;
    float4 ve[7], vs[7];
#pragma unroll
    for (int j = 0; j < 7; j++) {
        int r = ce * CH + j;
        ve[j] = make_float4(0.f, 0.f, 0.f, 0.f);
        if (r < e) ve[j] = fb[(size_t)r * D4];
    }
#pragma unroll
    for (int j = 0; j < 7; j++) {
        int r = cs * CH + j;
        vs[j] = make_float4(0.f, 0.f, 0.f, 0.f);
        if (r < s) vs[j] = fb[(size_t)r * D4];
    }
#pragma unroll
    for (int j = 0; j < 7; j++) {
        a.x += ve[j].x - vs[j].x;
        a.y += ve[j].y - vs[j].y;
        a.z += ve[j].z - vs[j].z;
        a.w += ve[j].w - vs[j].w;
    }
    float inv = 1.0f / (float)(e - s);
    a.x *= inv; a.y *= inv; a.z *= inv; a.w *= inv;

    __nv_bfloat162 h0, h1, l0, l1;
    h0.x = __float2bfloat16(a.x); h0.y = __float2bfloat16(a.y);
    h1.x = __float2bfloat16(a.z); h1.y = __float2bfloat16(a.w);
    l0.x = __float2bfloat16(a.x - __bfloat162float(h0.x));
    l0.y = __float2bfloat16(a.y - __bfloat162float(h0.y));
    l1.x = __float2bfloat16(a.z - __bfloat162float(h1.x));
    l1.y = __float2bfloat16(a.w - __bfloat162float(h1.y));
    size_t base = (size_t)bm * KIN + 4 * t;
    *(__nv_bfloat162*)(g_Xhi + base)     = h0;
    *(__nv_bfloat162*)(g_Xhi + base + 2) = h1;
    *(__nv_bfloat162*)(g_Xlo + base)     = l0;
    *(__nv_bfloat162*)(g_Xlo + base + 2) = l1;
}

// ---------------------------------------------------------------------------
// K4: split-bf16 mma.sync GEMM v4. Block 64x128, FOUR warps (2m x 2n, warp
// tile 32x64 keeps the 16-MMA : 6-LDSM ratio of v3), grid (64, 4) = 256
// blocks -> ~3 CTAs resident/SM (12 warps/SM from independent CTAs, so one
// CTA's __syncthreads doesn't stall the others' MMA issue). Round-14 ncu
// showed occ=12.6% (one fat CTA/SM) was the binding constraint.
// ---------------------------------------------------------------------------
__global__ void __launch_bounds__(128)
k_gemm(const float* __restrict__ bias, float* __restrict__ out) {
    __shared__ __align__(16) unsigned char As[2][64 * 80];    // [m64][k32] bf16, pitch 80 B
    __shared__ __align__(16) unsigned char Bs[2][32 * 272];   // [k32][n128] bf16, pitch 272 B

    int tid = threadIdx.x, wid = tid >> 5, l = tid & 31;
    int rbase = blockIdx.x * 64, cbase = blockIdx.y * 128;
    int mw = (wid & 1) * 32;      // warp m offset (32 rows)
    int nw = (wid >> 1) * 64;     // warp n offset (64 cols)

    // global load lanes: A 64 rows x 32 k = 4 KB -> 32 B/thread
    int arow = tid >> 1;                 // 0..63
    int ak = (tid & 1) * 16;             // 16 bf16 = 32 B half-row
    // B 32 k-rows x 128 n = 8 KB -> 64 B/thread
    int brow = tid >> 2;                 // 0..31
    int bn = (tid & 3) * 32;             // 32 bf16 = 64 B quarter-row

    const __nv_bfloat16* AP[3] = {
        g_Xhi + (size_t)(rbase + arow) * KIN + ak,
        g_Xhi + (size_t)(rbase + arow) * KIN + ak,
        g_Xlo + (size_t)(rbase + arow) * KIN + ak};
    const __nv_bfloat16* BP[3] = {
        g_Whi + (size_t)brow * DD + cbase + bn,
        g_Wlo + (size_t)brow * DD + cbase + bn,
        g_Whi + (size_t)brow * DD + cbase + bn};

    uint32_t asb = smem_u32(As), bsb = smem_u32(Bs);
    uint32_t ald = asb + (mw + (l & 15)) * 80 + (l >> 4) * 16;
    uint32_t bg = l >> 3;
    uint32_t bld = bsb + (((bg & 1) * 8) + (l & 7)) * 272 + (nw + (bg >> 1) * 8) * 2;

    float acc[2][8][4];
#pragma unroll
    for (int mt = 0; mt < 2; mt++)
#pragma unroll
        for (int nt = 0; nt < 8; nt++)
#pragma unroll
            for (int j = 0; j < 4; j++) acc[mt][nt][j] = 0.f;

    // preload iteration 0
    uint4 av0 = *(const uint4*)AP[0];
    uint4 av1 = *(const uint4*)(AP[0] + 8);
    uint4 bv0 = *(const uint4*)BP[0];
    uint4 bv1 = *(const uint4*)(BP[0] + 8);
    uint4 bv2 = *(const uint4*)(BP[0] + 16);
    uint4 bv3 = *(const uint4*)(BP[0] + 24);
    *(uint4*)(As[0] + arow * 80 + (tid & 1) * 32)      = av0;
    *(uint4*)(As[0] + arow * 80 + (tid & 1) * 32 + 16) = av1;
    {
        unsigned char* bs = Bs[0] + brow * 272 + (tid & 3) * 64;
        *(uint4*)(bs)      = bv0;
        *(uint4*)(bs + 16) = bv1;
        *(uint4*)(bs + 32) = bv2;
        *(uint4*)(bs + 48) = bv3;
    }
    __syncthreads();

    int p2 = 0, kt2 = 0;
    for (int it = 0; it < NIT; it++) {
        int cb = it & 1;
        if (it + 1 < NIT) {
            if (++kt2 == NKS) { kt2 = 0; p2++; }
            av0 = *(const uint4*)(AP[p2] + kt2 * 32);
            av1 = *(const uint4*)(AP[p2] + kt2 * 32 + 8);
            const __nv_bfloat16* bp = BP[p2] + (size_t)kt2 * 32 * DD;
            bv0 = *(const uint4*)(bp);
            bv1 = *(const uint4*)(bp + 8);
            bv2 = *(const uint4*)(bp + 16);
            bv3 = *(const uint4*)(bp + 24);
        }
        uint32_t ab = ald + cb * (64 * 80);
        uint32_t bb = bld + cb * (32 * 272);
#pragma unroll
        for (int kk = 0; kk < 2; kk++) {
            uint32_t a_f[2][4];
#pragma unroll
            for (int mt = 0; mt < 2; mt++)
                asm volatile("ldmatrix.sync.aligned.m8n8.x4.shared.b16 {%0,%1,%2,%3}, [%4];"
                             : "=r"(a_f[mt][0]), "=r"(a_f[mt][1]),
                               "=r"(a_f[mt][2]), "=r"(a_f[mt][3])
                             : "r"(ab + mt * 16 * 80 + kk * 32));
            uint32_t b_f[8][2];
#pragma unroll
            for (int pr = 0; pr < 4; pr++)
                asm volatile("ldmatrix.sync.aligned.m8n8.x4.trans.shared.b16 {%0,%1,%2,%3}, [%4];"
                             : "=r"(b_f[2 * pr][0]), "=r"(b_f[2 * pr][1]),
                               "=r"(b_f[2 * pr + 1][0]), "=r"(b_f[2 * pr + 1][1])
                             : "r"(bb + kk * (16 * 272) + pr * 32));
#pragma unroll
            for (int mt = 0; mt < 2; mt++)
#pragma unroll
                for (int nt = 0; nt < 8; nt++)
                    asm volatile(
                        "mma.sync.aligned.m16n8k16.row.col.f32.bf16.bf16.f32 "
                        "{%0,%1,%2,%3}, {%4,%5,%6,%7}, {%8,%9}, {%0,%1,%2,%3};"
                        : "+f"(acc[mt][nt][0]), "+f"(acc[mt][nt][1]),
                          "+f"(acc[mt][nt][2]), "+f"(acc[mt][nt][3])
                        : "r"(a_f[mt][0]), "r"(a_f[mt][1]), "r"(a_f[mt][2]), "r"(a_f[mt][3]),
                          "r"(b_f[nt][0]), "r"(b_f[nt][1]));
        }
        if (it + 1 < NIT) {
            int nb = cb ^ 1;
            *(uint4*)(As[nb] + arow * 80 + (tid & 1) * 32)      = av0;
            *(uint4*)(As[nb] + arow * 80 + (tid & 1) * 32 + 16) = av1;
            unsigned char* bs = Bs[nb] + brow * 272 + (tid & 3) * 64;
            *(uint4*)(bs)      = bv0;
            *(uint4*)(bs + 16) = bv1;
            *(uint4*)(bs + 32) = bv2;
            *(uint4*)(bs + 48) = bv3;
        }
        __syncthreads();
    }

    int g = l >> 2, tg = l & 3;
#pragma unroll
    for (int mt = 0; mt < 2; mt++) {
#pragma unroll
        for (int nt = 0; nt < 8; nt++) {
            int col = cbase + nw + nt * 8 + 2 * tg;
            float2 bb2 = *(const float2*)(bias + col);
            int r0 = rbase + mw + mt * 16 + g;
            float2 o0 = make_float2(acc[mt][nt][0] + bb2.x, acc[mt][nt][1] + bb2.y);
            float2 o1 = make_float2(acc[mt][nt][2] + bb2.x, acc[mt][nt][3] + bb2.y);
            *(float2*)(out + (size_t)r0 * DD + col) = o0;
            *(float2*)(out + (size_t)(r0 + 8) * DD + col) = o1;
        }
    }
}

// ---------------------------------------------------------------------------
extern "C" void kernel_launch(void* const* d_in, const int* in_sizes, int n_in,
                              void* d_out, int out_size) {
    const float* frame = (const float*)d_in[0];   // [8, 8192, 512] f32
    const void*  bb    = d_in[1];                 // [8, 512, 2] int32 or int64
    const float* W     = (const float*)d_in[2];   // [544, 512] f32
    const float* bias  = (const float*)d_in[3];   // [512] f32
    float* out = (float*)d_out;                   // [8, 512, 512] f32

    k_combo1<<<NB_SUM + NB_WS + NB_F + NB_BND, 256>>>((const float4*)frame, W, bb);
    k_gscan<<<128, 256>>>();
    k_seg<<<BB * MM, 128>>>((const float4*)frame);
    dim3 g(NROWS / 64, DD / 128);   // 64 x 4 = 256 blocks, 64-row tiles
    k_gemm<<<g, 128>>>(bias, out);
}

// round 17
// speedup vs baseline: 1.0525x; 1.0525x over previous
#include <cuda_runtime.h>
#include <cuda_bf16.h>
#include <cstdint>

#define BB 8
#define TT 8192
#define DD 512
#define MM 512
#define KIN 544        // DD + 32 fourier dims
#define CH 8           // rows per chunk
#define NC 1024        // TT / CH chunks per batch
#define GRP 8          // chunks per group
#define NG 128         // groups per batch (NC / GRP)
#define D4 128         // DD / 4
#define NROWS (BB*MM)  // 4096 output rows
#define NKS 17         // k32-steps per product (544/32)
#define NIT 51         // 3 products x 17
#define A_STG 10240    // A stage bytes (128*80)
#define B_STG 8704     // B stage bytes (32*272)

// combo1 block ranges
#define NB_SUM 512     // sumpre: 2 groups per block
#define NB_WS  1088    // wsplit (KIN*DD/256)
#define NB_F   64      // fourier
#define NB_BND 16      // bounds (4096/256)

// Scratch (allocation-free rule: __device__ globals)
__device__ float g_cpre[BB * NC * DD];        // 16.8 MB within-group exclusive chunk prefix
__device__ float g_gtot[BB * NG * DD];        //  2.1 MB group totals
__device__ float g_gpre[BB * (NG + 1) * DD];  //  2.1 MB exclusive group prefix
__device__ __nv_bfloat16 g_Xhi[NROWS * KIN];  //  4.5 MB X split-high [row][k]
__device__ __nv_bfloat16 g_Xlo[NROWS * KIN];  //  4.5 MB X split-low
__device__ __nv_bfloat16 g_Whi[KIN * DD];     //  0.56 MB W split-high [k][n]
__device__ __nv_bfloat16 g_Wlo[KIN * DD];     //  0.56 MB W split-low
__device__ int2  g_se  [NROWS];               // clamped (s, e) per segment

__device__ __forceinline__ uint32_t smem_u32(const void* p) {
    uint32_t a;
    asm("{ .reg .u64 t; cvta.to.shared.u64 t, %1; cvt.u32.u64 %0, t; }" : "=r"(a) : "l"(p));
    return a;
}

#define CP16(s, g)  asm volatile("cp.async.cg.shared.global [%0], [%1], 16;" :: "r"(s), "l"(g))
#define CPCOMMIT()  asm volatile("cp.async.commit_group;" ::: "memory")
#define CPWAIT0()   asm volatile("cp.async.wait_group 0;" ::: "memory")

// ---------------------------------------------------------------------------
// K_combo1: ONE launch for all independent front work (block-range dispatch).
// ---------------------------------------------------------------------------
__global__ void __launch_bounds__(256) k_combo1(const float4* __restrict__ fr,
                                                const float* __restrict__ W,
                                                const void* __restrict__ bbv) {
    int bid = blockIdx.x, tid = threadIdx.x;

    if (bid < NB_SUM) {
        int b = bid >> 6;
        int g = (bid & 63) * 2 + (tid >> 7);
        int t = tid & 127;
        const float4* p = fr + (size_t)(b * TT + g * GRP * CH) * D4 + t;
        float4* cp = (float4*)g_cpre + (size_t)(b * NC + g * GRP) * D4 + t;

        float4 run = make_float4(0.f, 0.f, 0.f, 0.f);
#pragma unroll
        for (int c = 0; c < GRP; c++) {
            cp[(size_t)c * D4] = run;
            float4 s = make_float4(0.f, 0.f, 0.f, 0.f);
#pragma unroll
            for (int r = 0; r < CH; r++) {
                float4 v = p[(size_t)(c * CH + r) * D4];
                s.x += v.x; s.y += v.y; s.z += v.z; s.w += v.w;
            }
            run.x += s.x; run.y += s.y; run.z += s.z; run.w += s.w;
        }
        ((float4*)g_gtot)[(size_t)(b * NG + g) * D4 + t] = run;

    } else if (bid < NB_SUM + NB_WS) {
        int i = (bid - NB_SUM) * 256 + tid;
        float v = W[i];
        __nv_bfloat16 h = __float2bfloat16(v);
        g_Whi[i] = h;
        g_Wlo[i] = __float2bfloat16(v - __bfloat162float(h));

    } else if (bid < NB_SUM + NB_WS + NB_F) {
        int m = (bid - NB_SUM - NB_WS) * 8 + (tid >> 5);
        int i = tid & 31;
        const float pos = (float)m * (1.0f / 511.0f);
        const float step = (float)(6.907755278982137 / 15.0);  // log(1000)/15
        int fi = (i < 16) ? i : i - 16;
        float arg = (float)fi * step;
        float freq = (float)exp((double)arg);
        float ang = pos * freq;
        double angd = (double)ang;
        float v = (i < 16) ? (float)sin(angd) : (float)cos(angd);
        __nv_bfloat16 h = __float2bfloat16(v);
        __nv_bfloat16 l = __float2bfloat16(v - __bfloat162float(h));
#pragma unroll
        for (int b = 0; b < BB; b++) {
            size_t idx = (size_t)(b * MM + m) * KIN + DD + i;
            g_Xhi[idx] = h;
            g_Xlo[idx] = l;
        }

    } else {
        __shared__ int s_any;
        if (tid == 0) s_any = 0;
        __syncthreads();
        const unsigned int* bbw = (const unsigned int*)bbv;
        int bad = 0;
        for (int i = 2 * tid + 1; i < BB * MM * 2; i += 2 * 256)
            if (bbw[i] != 0u) bad = 1;
        if (bad) atomicOr(&s_any, 1);
        __syncthreads();
        int is64 = (s_any == 0);

        int bm = (bid - NB_SUM - NB_WS - NB_F) * 256 + tid;
        long long s_raw, e_raw;
        if (is64) {
            const long long* p = (const long long*)bbv;
            s_raw = p[2 * bm]; e_raw = p[2 * bm + 1];
        } else {
            const int* p = (const int*)bbv;
            s_raw = p[2 * bm]; e_raw = p[2 * bm + 1];
        }
        long long sl = s_raw; if (sl < 0) sl = 0; if (sl > TT - 1) sl = TT - 1;
        long long el = e_raw; if (el > TT) el = TT; if (el < sl + 1) el = sl + 1;
        g_se[bm] = make_int2((int)sl, (int)el);
    }
}

// ---------------------------------------------------------------------------
// K2: warp-parallel exclusive prefix over 128 group totals.
// ---------------------------------------------------------------------------
__global__ void __launch_bounds__(256) k_gscan() {
    int wid = threadIdx.x >> 5, l = threadIdx.x & 31;
    int b  = blockIdx.x >> 4;
    int c4 = (blockIdx.x & 15) * 8 + wid;
    const float4* gt = (const float4*)g_gtot + (size_t)b * NG * D4 + c4;
    float4* gp = (float4*)g_gpre + (size_t)b * (NG + 1) * D4 + c4;

    float4 v[4];
    float4 s = make_float4(0.f, 0.f, 0.f, 0.f);
#pragma unroll
    for (int j = 0; j < 4; j++) {
        v[j] = gt[(size_t)(4 * l + j) * D4];
        s.x += v[j].x; s.y += v[j].y; s.z += v[j].z; s.w += v[j].w;
    }
    float4 inc = s;
#pragma unroll
    for (int off = 1; off < 32; off <<= 1) {
        float ux = __shfl_up_sync(0xffffffffu, inc.x, off);
        float uy = __shfl_up_sync(0xffffffffu, inc.y, off);
        float uz = __shfl_up_sync(0xffffffffu, inc.z, off);
        float uw = __shfl_up_sync(0xffffffffu, inc.w, off);
        if (l >= off) { inc.x += ux; inc.y += uy; inc.z += uz; inc.w += uw; }
    }
    float4 run = make_float4(inc.x - s.x, inc.y - s.y, inc.z - s.z, inc.w - s.w);
#pragma unroll
    for (int j = 0; j < 4; j++) {
        gp[(size_t)(4 * l + j) * D4] = run;
        run.x += v[j].x; run.y += v[j].y; run.z += v[j].z; run.w += v[j].w;
    }
    if (l == 31) gp[(size_t)NG * D4] = run;
}

// ---------------------------------------------------------------------------
// K3: per-segment mean -> bf16 hi/lo into g_Xhi/g_Xlo cols 0..511.
// ---------------------------------------------------------------------------
__global__ void __launch_bounds__(128) k_seg(const float4* __restrict__ fr) {
    int bm = blockIdx.x;
    int b = bm >> 9;

    int2 se = g_se[bm];
    int s = se.x, e = se.y;
    int cs = s >> 3, ce = e >> 3;

    int t = threadIdx.x;
    const float4* CP = (const float4*)g_cpre + (size_t)b * NC * D4 + t;
    const float4* GP = (const float4*)g_gpre + (size_t)b * (NG + 1) * D4 + t;

    float4 a = GP[(size_t)(ce >> 3) * D4];
    float4 q = GP[(size_t)(cs >> 3) * D4];
    {
        float4 c1 = CP[(size_t)cs * D4];
        q.x += c1.x; q.y += c1.y; q.z += c1.z; q.w += c1.w;
        if (ce < NC) {
            float4 c2 = CP[(size_t)ce * D4];
            a.x += c2.x; a.y += c2.y; a.z += c2.z; a.w += c2.w;
        }
    }
    a.x -= q.x; a.y -= q.y; a.z -= q.z; a.w -= q.w;

    const float4* fb = fr + (size_t)b * TT * D4 + t;
    float4 ve[7], vs[7];
#pragma unroll
    for (int j = 0; j < 7; j++) {
        int r = ce * CH + j;
        ve[j] = make_float4(0.f, 0.f, 0.f, 0.f);
        if (r < e) ve[j] = fb[(size_t)r * D4];
    }
#pragma unroll
    for (int j = 0; j < 7; j++) {
        int r = cs * CH + j;
        vs[j] = make_float4(0.f, 0.f, 0.f, 0.f);
        if (r < s) vs[j] = fb[(size_t)r * D4];
    }
#pragma unroll
    for (int j = 0; j < 7; j++) {
        a.x += ve[j].x - vs[j].x;
        a.y += ve[j].y - vs[j].y;
        a.z += ve[j].z - vs[j].z;
        a.w += ve[j].w - vs[j].w;
    }
    float inv = 1.0f / (float)(e - s);
    a.x *= inv; a.y *= inv; a.z *= inv; a.w *= inv;

    __nv_bfloat162 h0, h1, l0, l1;
    h0.x = __float2bfloat16(a.x); h0.y = __float2bfloat16(a.y);
    h1.x = __float2bfloat16(a.z); h1.y = __float2bfloat16(a.w);
    l0.x = __float2bfloat16(a.x - __bfloat162float(h0.x));
    l0.y = __float2bfloat16(a.y - __bfloat162float(h0.y));
    l1.x = __float2bfloat16(a.z - __bfloat162float(h1.x));
    l1.y = __float2bfloat16(a.w - __bfloat162float(h1.y));
    size_t base = (size_t)bm * KIN + 4 * t;
    *(__nv_bfloat162*)(g_Xhi + base)     = h0;
    *(__nv_bfloat162*)(g_Xhi + base + 2) = h1;
    *(__nv_bfloat162*)(g_Xlo + base)     = l0;
    *(__nv_bfloat162*)(g_Xlo + base + 2) = l1;
}

// ---------------------------------------------------------------------------
// K4: split-bf16 mma.sync GEMM v5 = round-14 shape (128x128 tile, 8 warps
// 4m x 2n, warp tile 32x64, grid 32x4) + cp.async double-buffering:
// gmem->smem goes direct (cp.async.cg, one commit group per k32 iteration),
// issued right after the single __syncthreads and overlapped with a full
// compute block. Removes the LDG->reg->STS exposure that made round-14
// spend ~1300 of 1800 cyc/iter outside the tensor pipe (tensor=23.7%).
// ---------------------------------------------------------------------------
__global__ void __launch_bounds__(256)
k_gemm(const float* __restrict__ bias, float* __restrict__ out) {
    __shared__ __align__(16) unsigned char As[2][A_STG];   // [m128][k32] bf16, pitch 80 B
    __shared__ __align__(16) unsigned char Bs[2][B_STG];   // [k32][n128] bf16, pitch 272 B

    int tid = threadIdx.x, wid = tid >> 5, l = tid & 31;
    int rbase = blockIdx.x * 128, cbase = blockIdx.y * 128;
    int mw = (wid & 3) * 32;      // warp m offset
    int nw = (wid >> 2) * 64;     // warp n offset

    int arow = tid >> 1;                 // 0..127
    int ak = (tid & 1) * 16;             // 16 bf16 = 32 B half-row
    int brow = tid >> 3;                 // 0..31
    int bn = (tid & 7) * 16;             // n element offset

    const __nv_bfloat16* AP[3] = {
        g_Xhi + (size_t)(rbase + arow) * KIN + ak,
        g_Xhi + (size_t)(rbase + arow) * KIN + ak,
        g_Xlo + (size_t)(rbase + arow) * KIN + ak};
    const __nv_bfloat16* BP[3] = {
        g_Whi + (size_t)brow * DD + cbase + bn,
        g_Wlo + (size_t)brow * DD + cbase + bn,
        g_Whi + (size_t)brow * DD + cbase + bn};

    uint32_t asb = smem_u32(As), bsb = smem_u32(Bs);
    uint32_t a_st = asb + arow * 80 + (tid & 1) * 32;   // buffer-0 store addr
    uint32_t b_st = bsb + brow * 272 + (tid & 7) * 32;
    uint32_t ald = asb + (mw + (l & 15)) * 80 + (l >> 4) * 16;
    uint32_t bg = l >> 3;
    uint32_t bld = bsb + (((bg & 1) * 8) + (l & 7)) * 272 + (nw + (bg >> 1) * 8) * 2;

    float acc[2][8][4];
#pragma unroll
    for (int mt = 0; mt < 2; mt++)
#pragma unroll
        for (int nt = 0; nt < 8; nt++)
#pragma unroll
            for (int j = 0; j < 4; j++) acc[mt][nt][j] = 0.f;

    // prologue: stage 0 loads via cp.async
    CP16(a_st, AP[0]); CP16(a_st + 16, AP[0] + 8);
    CP16(b_st, BP[0]); CP16(b_st + 16, BP[0] + 8);
    CPCOMMIT();

    int pl = 0, ktl = 0;   // load-ahead indices
    for (int it = 0; it < NIT; it++) {
        int cb = it & 1;
        CPWAIT0();            // stage-it data arrived (overlapped with it-1 compute)
        __syncthreads();      // visible to all; buffer cb^1 free (it-1 compute done)
        if (it + 1 < NIT) {   // issue stage it+1 BEFORE compute -> overlaps MMA
            if (++ktl == NKS) { ktl = 0; pl++; }
            const __nv_bfloat16* ap = AP[pl] + ktl * 32;
            const __nv_bfloat16* bp = BP[pl] + (size_t)ktl * 32 * DD;
            uint32_t a2 = a_st + (cb ^ 1) * A_STG;
            uint32_t b2 = b_st + (cb ^ 1) * B_STG;
            CP16(a2, ap); CP16(a2 + 16, ap + 8);
            CP16(b2, bp); CP16(b2 + 16, bp + 8);
            CPCOMMIT();
        }
        uint32_t ab = ald + cb * A_STG;
        uint32_t bb = bld + cb * B_STG;
#pragma unroll
        for (int kk = 0; kk < 2; kk++) {
            uint32_t a_f[2][4];
#pragma unroll
            for (int mt = 0; mt < 2; mt++)
                asm volatile("ldmatrix.sync.aligned.m8n8.x4.shared.b16 {%0,%1,%2,%3}, [%4];"
                             : "=r"(a_f[mt][0]), "=r"(a_f[mt][1]),
                               "=r"(a_f[mt][2]), "=r"(a_f[mt][3])
                             : "r"(ab + mt * 16 * 80 + kk * 32));
            uint32_t b_f[8][2];
#pragma unroll
            for (int pr = 0; pr < 4; pr++)
                asm volatile("ldmatrix.sync.aligned.m8n8.x4.trans.shared.b16 {%0,%1,%2,%3}, [%4];"
                             : "=r"(b_f[2 * pr][0]), "=r"(b_f[2 * pr][1]),
                               "=r"(b_f[2 * pr + 1][0]), "=r"(b_f[2 * pr + 1][1])
                             : "r"(bb + kk * (16 * 272) + pr * 32));
#pragma unroll
            for (int mt = 0; mt < 2; mt++)
#pragma unroll
                for (int nt = 0; nt < 8; nt++)
                    asm volatile(
                        "mma.sync.aligned.m16n8k16.row.col.f32.bf16.bf16.f32 "
                        "{%0,%1,%2,%3}, {%4,%5,%6,%7}, {%8,%9}, {%0,%1,%2,%3};"
                        : "+f"(acc[mt][nt][0]), "+f"(acc[mt][nt][1]),
                          "+f"(acc[mt][nt][2]), "+f"(acc[mt][nt][3])
                        : "r"(a_f[mt][0]), "r"(a_f[mt][1]), "r"(a_f[mt][2]), "r"(a_f[mt][3]),
                          "r"(b_f[nt][0]), "r"(b_f[nt][1]));
        }
        __syncthreads();
    }

    int g = l >> 2, tg = l & 3;
#pragma unroll
    for (int mt = 0; mt < 2; mt++) {
#pragma unroll
        for (int nt = 0; nt < 8; nt++) {
            int col = cbase + nw + nt * 8 + 2 * tg;
            float2 bv2 = *(const float2*)(bias + col);
            int r0 = rbase + mw + mt * 16 + g;
            float2 o0 = make_float2(acc[mt][nt][0] + bv2.x, acc[mt][nt][1] + bv2.y);
            float2 o1 = make_float2(acc[mt][nt][2] + bv2.x, acc[mt][nt][3] + bv2.y);
            *(float2*)(out + (size_t)r0 * DD + col) = o0;
            *(float2*)(out + (size_t)(r0 + 8) * DD + col) = o1;
        }
    }
}

// ---------------------------------------------------------------------------
extern "C" void kernel_launch(void* const* d_in, const int* in_sizes, int n_in,
                              void* d_out, int out_size) {
    const float* frame = (const float*)d_in[0];   // [8, 8192, 512] f32
    const void*  bb    = d_in[1];                 // [8, 512, 2] int32 or int64
    const float* W     = (const float*)d_in[2];   // [544, 512] f32
    const float* bias  = (const float*)d_in[3];   // [512] f32
    float* out = (float*)d_out;                   // [8, 512, 512] f32

    k_combo1<<<NB_SUM + NB_WS + NB_F + NB_BND, 256>>>((const float4*)frame, W, bb);
    k_gscan<<<128, 256>>>();
    k_seg<<<BB * MM, 128>>>((const float4*)frame);
    dim3 g(NROWS / 128, DD / 128);   // 32 x 4 blocks, 128-row tiles
    k_gemm<<<g, 256>>>(bias, out);
}